// round 6
// baseline (speedup 1.0000x reference)
#include <cuda_runtime.h>
#include <math.h>

// Problem constants
#define B_ 2
#define CC 512      // concat channels
#define CO 256      // output channels
#define C1 512      // x1 channels
#define H_ 64
#define W_ 64
#define HW 4096
#define HWIN 1024
#define OFFC 18
#define K2 9

typedef unsigned long long ull;

// Packed f32x2 helpers (Blackwell FFMA2 path)
__device__ __forceinline__ ull pack2(float lo, float hi) {
    ull r; asm("mov.b64 %0, {%1,%2};" : "=l"(r) : "f"(lo), "f"(hi)); return r;
}
__device__ __forceinline__ void fma2(ull& d, ull a, ull b) {
    asm("fma.rn.f32x2 %0, %1, %2, %0;" : "+l"(d) : "l"(a), "l"(b));
}
__device__ __forceinline__ float2 unpack2(ull v) {
    float2 r; asm("mov.b64 {%0,%1}, %2;" : "=f"(r.x), "=f"(r.y) : "l"(v)); return r;
}

// Scratch (device globals; no runtime allocation)
__device__ float g_t[B_ * CO * HWIN];          // 1x1-conv'd x1 @ 32x32 (no bias)
__device__ __align__(16) float g_x[B_ * CC * HW];  // concat tensor
__device__ float g_offp[B_ * 4 * OFFC * HW];   // offset partials (4 ci-chunks)
__device__ float g_dc[B_ * CO * HW];           // deform conv output (+def_b)
__device__ __align__(16) float g_wT[K2 * CC * CO + 256];  // def_w [k][ci][co]
__device__ float g_stats[2 * CO];              // mean, rstd per channel

// ---------------------------------------------------------------------------
// #1: 1x1 conv on x1 at 32x32 (transposed weight staging + FFMA2)
__global__ void k_upconv(const float* __restrict__ x1,
                         const float* __restrict__ up_w) {
    __shared__ __align__(16) float ws[8 * 512];   // [ci][j]
    int b = blockIdx.z;
    int co0 = blockIdx.y * 8;
    int p = blockIdx.x * 128 + threadIdx.x;
    for (int i = threadIdx.x; i < 4096; i += 128) {
        int j = i >> 9, ci = i & 511;
        ws[ci * 8 + j] = up_w[(co0 + j) * 512 + ci];
    }
    __syncthreads();
    ull a[4] = {0ull, 0ull, 0ull, 0ull};
    const float* xp = x1 + b * C1 * HWIN + p;
#pragma unroll 4
    for (int ci = 0; ci < 512; ci++) {
        float xv = __ldg(xp + ci * HWIN);
        ull xv2 = pack2(xv, xv);
        const ull* wr = (const ull*)(ws + ci * 8);
        fma2(a[0], wr[0], xv2);
        fma2(a[1], wr[1], xv2);
        fma2(a[2], wr[2], xv2);
        fma2(a[3], wr[3], xv2);
    }
#pragma unroll
    for (int jp = 0; jp < 4; jp++) {
        float2 u = unpack2(a[jp]);
        g_t[(b * CO + co0 + 2 * jp) * HWIN + p] = u.x;
        g_t[(b * CO + co0 + 2 * jp + 1) * HWIN + p] = u.y;
    }
}

// ---------------------------------------------------------------------------
// #2: fused copy (x2 -> g_x[0:256)) + bilinear upsample (g_t -> g_x[256:512))
#define COPY_BLKS 2048
__global__ void k_copyup(const float* __restrict__ x2,
                         const float* __restrict__ up_b) {
    int blk = blockIdx.x;
    if (blk < COPY_BLKS) {
        int i = blk * 256 + threadIdx.x;          // float4 index < 524288
        int b = i >> 18;
        int c = (i >> 10) & 255;
        int p4 = i & 1023;
        ((float4*)g_x)[((b * 512) + c) * 1024 + p4] = ((const float4*)x2)[i];
        return;
    }
    int idx = (blk - COPY_BLKS) * 256 + threadIdx.x;
    if (idx >= B_ * CO * HW) return;
    int p = idx & (HW - 1);
    int c = (idx >> 12) & (CO - 1);
    int b = idx >> 20;
    int h = p >> 6, w = p & 63;
    const float scale = 31.0f / 63.0f;
    float fh = h * scale;
    int i0 = (int)floorf(fh); if (i0 > 30) i0 = 30;
    float wy = fh - (float)i0;
    float fw = w * scale;
    int j0 = (int)floorf(fw); if (j0 > 30) j0 = 30;
    float wx = fw - (float)j0;
    const float* tt = g_t + (idx >> 12) * HWIN;
    float v00 = tt[i0 * 32 + j0];
    float v01 = tt[i0 * 32 + j0 + 1];
    float v10 = tt[(i0 + 1) * 32 + j0];
    float v11 = tt[(i0 + 1) * 32 + j0 + 1];
    float v = (1.f - wy) * ((1.f - wx) * v00 + wx * v01) +
              wy * ((1.f - wx) * v10 + wx * v11);
    g_x[((b * 512) + 256 + c) * HW + p] = v + up_b[c];
}

// ---------------------------------------------------------------------------
// #3: fused def_w transpose + offset-conv partials.
// Blocks [0,4608): wt role. Blocks [4608,4736): offconv role, 256 threads =
// 4 row-groups of 64.
#define WT_BLKS 4608
__global__ void __launch_bounds__(256) k_offwt(const float* __restrict__ def_w,
                                               const float* __restrict__ off_w) {
    if (blockIdx.x < WT_BLKS) {
        int i = blockIdx.x * 256 + threadIdx.x;   // < K2*CC*CO
        int co = i & 255;
        int ci = (i >> 8) & 511;
        int k = i >> 17;
        g_wT[i] = def_w[(co * 512 + ci) * 9 + k];
        return;
    }
    __shared__ __align__(16) float xr[4][8][3][66];
    __shared__ __align__(16) float wsh[8][9 * 18];
    int r = blockIdx.x - WT_BLKS;                 // 0..127
    int b = r >> 6;
    int rr = r & 63;
    int cc = rr >> 4;
    int h0 = (rr & 15) * 4;
    int t = threadIdx.x;
    int g = t >> 6;                               // row group 0..3
    int tl = t & 63;
    int h = h0 + g;
    int ci0 = cc * 128;
    ull a[9];
#pragma unroll
    for (int c = 0; c < 9; c++) a[c] = 0ull;
    for (int s8 = 0; s8 < 128; s8 += 8) {
        // stage transposed weights (shared across the 4 row groups)
        for (int idx = t; idx < 8 * 162; idx += 256) {
            int ciL = idx / 162;
            int rem = idx - ciL * 162;
            int tap = rem / 18;
            int c = rem - tap * 18;
            int ci = ci0 + s8 + ciL;
            wsh[ciL][rem] = off_w[(c * 512 + ci) * 9 + tap];
        }
        // stage input rows (per group)
        for (int idx = tl; idx < 8 * 198; idx += 64) {
            int ciL = idx / 198;
            int rem = idx - ciL * 198;
            int rrow = rem / 66;
            int c66 = rem - rrow * 66;
            int cw = c66 - 1;
            int y = h - 1 + rrow;
            const float* pl = g_x + ((b * 512 + ci0 + s8 + ciL) << 12);
            xr[g][ciL][rrow][c66] = (y >= 0 && y < 64 && cw >= 0 && cw < 64)
                                        ? pl[y * 64 + cw] : 0.f;
        }
        __syncthreads();
#pragma unroll 2
        for (int ciL = 0; ciL < 8; ciL++) {
#pragma unroll
            for (int tap = 0; tap < 9; tap++) {
                float xv = xr[g][ciL][tap / 3][tl + tap % 3];
                ull xv2 = pack2(xv, xv);
                const ull* wr = (const ull*)&wsh[ciL][tap * 18];
#pragma unroll
                for (int c2 = 0; c2 < 9; c2++) fma2(a[c2], wr[c2], xv2);
            }
        }
        __syncthreads();
    }
#pragma unroll
    for (int c2 = 0; c2 < 9; c2++) {
        float2 u = unpack2(a[c2]);
        float* dst = g_offp + ((b * 4 + cc) * OFFC) * HW + h * 64 + tl;
        dst[(2 * c2) * HW] = u.x;
        dst[(2 * c2 + 1) * HW] = u.y;
    }
}

// ---------------------------------------------------------------------------
// #4: deformable conv, software-pipelined, dedup-free FFMA2.
// 128 threads: thread t -> co quad 4*(t&63) (one LDG.128 = 2 ull co-pairs),
// pixel slice (t>>6)*8. Pixels stored DUPLICATED in shared (float2(v,v)) so
// the FMA loop has zero packing MOVs. Offset partials summed inline.
#define PIX 16
#define CICHUNK 64
#define NITER 72
__global__ void __launch_bounds__(128) k_deform(const float* __restrict__ off_b,
                                                const float* __restrict__ def_b) {
    __shared__ __align__(16) float2 v2[2][CICHUNK][PIX];
    __shared__ __align__(16) int4 offs[K2][PIX];
    __shared__ __align__(16) float4 cws[K2][PIX];
    int b = blockIdx.y;
    int p0 = blockIdx.x * PIX;
    int t = threadIdx.x;
    int tco = t & 63;
    int tp = t >> 6;                 // 0..1 -> pixels tp*8..tp*8+7
    const float* xb = g_x + (b * 512) * HW;

    // Bilinear metadata for all 9 taps x 16 pixels; offset = bias + 4 partials
    for (int e = t; e < K2 * PIX; e += 128) {
        int k = e >> 4;
        int pi = e & 15;
        int p = p0 + pi;
        int h = p >> 6, w = p & 63;
        float dy = off_b[2 * k];
        float dx = off_b[2 * k + 1];
#pragma unroll
        for (int cc = 0; cc < 4; cc++) {
            const float* pp = g_offp + ((b * 4 + cc) * OFFC) * HW + p;
            dy += pp[(2 * k) * HW];
            dx += pp[(2 * k + 1) * HW];
        }
        float py = (float)h + (float)(k / 3) - 1.f + dy;
        float px = (float)w + (float)(k % 3) - 1.f + dx;
        float fy = floorf(py), fx = floorf(px);
        float wy = py - fy, wx = px - fx;
        int y0 = (int)fy, x0 = (int)fx;
        int y1 = y0 + 1, x1 = x0 + 1;
        bool vy0 = (unsigned)y0 < 64u, vy1 = (unsigned)y1 < 64u;
        bool vx0 = (unsigned)x0 < 64u, vx1 = (unsigned)x1 < 64u;
        int y0c = min(max(y0, 0), 63), y1c = min(max(y1, 0), 63);
        int x0c = min(max(x0, 0), 63), x1c = min(max(x1, 0), 63);
        cws[k][pi] = make_float4((vy0 && vx0) ? (1.f - wy) * (1.f - wx) : 0.f,
                                 (vy0 && vx1) ? (1.f - wy) * wx : 0.f,
                                 (vy1 && vx0) ? wy * (1.f - wx) : 0.f,
                                 (vy1 && vx1) ? wy * wx : 0.f);
        offs[k][pi] = make_int4(y0c * 64 + x0c, y0c * 64 + x1c,
                                y1c * 64 + x0c, y1c * 64 + x1c);
    }
    __syncthreads();

    ull acc[8][2];                  // [pixel][co-pair]
#pragma unroll
    for (int p = 0; p < 8; p++) { acc[p][0] = 0ull; acc[p][1] = 0ull; }

    float r[32];
    // Prologue: gather iteration 0 (k=0, c0=0) into buffer 0
#pragma unroll
    for (int j = 0; j < 8; j++) {
        int e = t + j * 128;
        int pi = e & 15;
        int cl = e >> 4;
        int4 o = offs[0][pi];
        const float* pl = xb + (cl << 12);
        r[4 * j + 0] = __ldg(pl + o.x);
        r[4 * j + 1] = __ldg(pl + o.y);
        r[4 * j + 2] = __ldg(pl + o.z);
        r[4 * j + 3] = __ldg(pl + o.w);
    }
#pragma unroll
    for (int j = 0; j < 8; j++) {
        int e = t + j * 128;
        int pi = e & 15;
        int cl = e >> 4;
        float4 cw = cws[0][pi];
        float v = cw.x * r[4 * j] + cw.y * r[4 * j + 1] +
                  cw.z * r[4 * j + 2] + cw.w * r[4 * j + 3];
        v2[0][cl][pi] = make_float2(v, v);
    }
    __syncthreads();

    int k = 0, c0 = 0;
    for (int i = 0; i < NITER; i++) {
        int buf = i & 1;
        int kn = k, c0n = c0 + CICHUNK;
        if (c0n == CC) { c0n = 0; kn = k + 1; }
        // Gather LDGs for iteration i+1 (latency hidden by FMA below)
        if (i + 1 < NITER) {
            const float* basen = xb + c0n * HW;
#pragma unroll
            for (int j = 0; j < 8; j++) {
                int e = t + j * 128;
                int pi = e & 15;
                int cl = e >> 4;
                int4 o = offs[kn][pi];
                const float* pl = basen + (cl << 12);
                r[4 * j + 0] = __ldg(pl + o.x);
                r[4 * j + 1] = __ldg(pl + o.y);
                r[4 * j + 2] = __ldg(pl + o.z);
                r[4 * j + 3] = __ldg(pl + o.w);
            }
        }
        // FMA phase: weights as raw ull co-pairs, pixels pre-duplicated
        const ulonglong2* wp =
            (const ulonglong2*)(g_wT + (k * CC + c0) * CO) + tco;
        const ulonglong2* vbase = (const ulonglong2*)&v2[buf][0][tp * 8];
#pragma unroll 4
        for (int cl = 0; cl < CICHUNK; cl++) {
            ulonglong2 wv = __ldg(wp + cl * 64);
            const ulonglong2* vv = vbase + cl * (PIX / 2);
#pragma unroll
            for (int q = 0; q < 4; q++) {
                ulonglong2 d = vv[q];
                fma2(acc[2 * q][0], wv.x, d.x);
                fma2(acc[2 * q][1], wv.y, d.x);
                fma2(acc[2 * q + 1][0], wv.x, d.y);
                fma2(acc[2 * q + 1][1], wv.y, d.y);
            }
        }
        // Combine gathered corners into the other buffer (duplicated)
        if (i + 1 < NITER) {
#pragma unroll
            for (int j = 0; j < 8; j++) {
                int e = t + j * 128;
                int pi = e & 15;
                int cl = e >> 4;
                float4 cw = cws[kn][pi];
                float v = cw.x * r[4 * j] + cw.y * r[4 * j + 1] +
                          cw.z * r[4 * j + 2] + cw.w * r[4 * j + 3];
                v2[buf ^ 1][cl][pi] = make_float2(v, v);
            }
        }
        __syncthreads();
        k = kn; c0 = c0n;
    }

    // Epilogue: acc[p][0] = (co0,co1) @ pixel p; acc[p][1] = (co2,co3)
#pragma unroll
    for (int j = 0; j < 4; j++) {
        int co = 4 * tco + j;
        float bb = def_b[co];
        float* o = g_dc + (b * CO + co) * HW + p0 + tp * 8;
        float vals[8];
#pragma unroll
        for (int p = 0; p < 8; p++) {
            float2 u = unpack2(acc[p][j >> 1]);
            vals[p] = ((j & 1) ? u.y : u.x) + bb;
        }
        ((float4*)o)[0] = make_float4(vals[0], vals[1], vals[2], vals[3]);
        ((float4*)o)[1] = make_float4(vals[4], vals[5], vals[6], vals[7]);
    }
}

// ---------------------------------------------------------------------------
// #5: BN stats (deterministic tree reduction)
__global__ void k_stats() {
    int co = blockIdx.x, t = threadIdx.x;
    const float* p0 = g_dc + co * HW;
    const float* p1 = g_dc + (CO + co) * HW;
    float s = 0.f, s2 = 0.f;
    for (int i = t; i < HW; i += 256) {
        float v = p0[i]; s += v; s2 += v * v;
        v = p1[i]; s += v; s2 += v * v;
    }
    __shared__ float sh[256], sh2[256];
    sh[t] = s; sh2[t] = s2;
    __syncthreads();
    for (int o = 128; o > 0; o >>= 1) {
        if (t < o) { sh[t] += sh[t + o]; sh2[t] += sh2[t + o]; }
        __syncthreads();
    }
    if (t == 0) {
        float m = sh[0] * (1.f / 8192.f);
        float var = sh2[0] * (1.f / 8192.f) - m * m;
        g_stats[co] = m;
        g_stats[CO + co] = rsqrtf(var + 1e-5f);
    }
}

// ---------------------------------------------------------------------------
// #6: shortcut 1x1 conv + BN apply + relu
__global__ void k_final(const float* __restrict__ sc_w,
                        const float* __restrict__ sc_b,
                        const float* __restrict__ gamma,
                        const float* __restrict__ beta,
                        float* __restrict__ out) {
    __shared__ __align__(16) float ws[8 * 512];   // [ci][j]
    int b = blockIdx.z;
    int co0 = blockIdx.y * 8;
    int p = blockIdx.x * 128 + threadIdx.x;
    for (int i = threadIdx.x; i < 4096; i += 128) {
        int j = i >> 9, ci = i & 511;
        ws[ci * 8 + j] = sc_w[(co0 + j) * 512 + ci];
    }
    __syncthreads();
    ull a[4] = {0ull, 0ull, 0ull, 0ull};
    const float* xp = g_x + b * 512 * HW + p;
#pragma unroll 4
    for (int ci = 0; ci < 512; ci++) {
        float xv = __ldg(xp + ci * HW);
        ull xv2 = pack2(xv, xv);
        const ull* wr = (const ull*)(ws + ci * 8);
        fma2(a[0], wr[0], xv2);
        fma2(a[1], wr[1], xv2);
        fma2(a[2], wr[2], xv2);
        fma2(a[3], wr[3], xv2);
    }
#pragma unroll
    for (int jp = 0; jp < 4; jp++) {
        float2 u = unpack2(a[jp]);
#pragma unroll
        for (int half = 0; half < 2; half++) {
            int co = co0 + 2 * jp + half;
            float accv = half ? u.y : u.x;
            float m = g_stats[co], r = g_stats[CO + co];
            float v = (g_dc[(b * CO + co) * HW + p] - m) * r * gamma[co] +
                      beta[co] + accv + sc_b[co];
            out[(b * CO + co) * HW + p] = fmaxf(v, 0.f);
        }
    }
}

// ---------------------------------------------------------------------------
extern "C" void kernel_launch(void* const* d_in, const int* in_sizes, int n_in,
                              void* d_out, int out_size) {
    const float* x1    = (const float*)d_in[0];
    const float* x2    = (const float*)d_in[1];
    const float* up_w  = (const float*)d_in[2];
    const float* up_b  = (const float*)d_in[3];
    const float* off_w = (const float*)d_in[4];
    const float* off_b = (const float*)d_in[5];
    const float* def_w = (const float*)d_in[6];
    const float* def_b = (const float*)d_in[7];
    const float* bn_g  = (const float*)d_in[8];
    const float* bn_b  = (const float*)d_in[9];
    const float* sc_w  = (const float*)d_in[10];
    const float* sc_b  = (const float*)d_in[11];
    float* out = (float*)d_out;

    k_upconv<<<dim3(HWIN / 128, CO / 8, B_), 128>>>(x1, up_w);
    k_copyup<<<COPY_BLKS + (B_ * CO * HW + 255) / 256, 256>>>(x2, up_b);
    k_offwt<<<WT_BLKS + 128, 256>>>(def_w, off_w);
    k_deform<<<dim3(HW / PIX, B_), 128>>>(off_b, def_b);
    k_stats<<<CO, 256>>>();
    k_final<<<dim3(HW / 128, CO / 8, B_), 128>>>(sc_w, sc_b, bn_g, bn_b, out);
}

// round 7
// speedup vs baseline: 1.2536x; 1.2536x over previous
#include <cuda_runtime.h>
#include <math.h>

// Problem constants
#define B_ 2
#define CC 512      // concat channels
#define CO 256      // output channels
#define C1 512      // x1 channels
#define H_ 64
#define W_ 64
#define HW 4096
#define HWIN 1024
#define OFFC 18
#define K2 9
#define KG 3        // tap groups (split-k)
#define BCOHW (B_ * CO * HW)

typedef unsigned long long ull;

// Packed f32x2 helpers (Blackwell FFMA2 path)
__device__ __forceinline__ ull pack2(float lo, float hi) {
    ull r; asm("mov.b64 %0, {%1,%2};" : "=l"(r) : "f"(lo), "f"(hi)); return r;
}
__device__ __forceinline__ void fma2(ull& d, ull a, ull b) {
    asm("fma.rn.f32x2 %0, %1, %2, %0;" : "+l"(d) : "l"(a), "l"(b));
}
__device__ __forceinline__ float2 unpack2(ull v) {
    float2 r; asm("mov.b64 {%0,%1}, %2;" : "=f"(r.x), "=f"(r.y) : "l"(v)); return r;
}

// Scratch (device globals; no runtime allocation)
__device__ float g_t[B_ * CO * HWIN];          // 1x1-conv'd x1 @ 32x32 (no bias)
__device__ __align__(16) float g_x[B_ * CC * HW];  // concat tensor
__device__ float g_offp[B_ * 4 * OFFC * HW];   // offset partials (4 ci-chunks)
__device__ __align__(16) float g_dcp[KG * BCOHW];  // deform partials (3 tap-groups)
__device__ float g_dc[BCOHW];                  // deform conv output (+def_b)
__device__ __align__(16) float g_wT[K2 * CC * CO + 256];  // def_w [k][ci][co]
__device__ float g_stats[2 * CO];              // mean, rstd per channel

// ---------------------------------------------------------------------------
// #1: 1x1 conv on x1 at 32x32 (transposed weight staging + FFMA2)
__global__ void k_upconv(const float* __restrict__ x1,
                         const float* __restrict__ up_w) {
    __shared__ __align__(16) float ws[8 * 512];   // [ci][j]
    int b = blockIdx.z;
    int co0 = blockIdx.y * 8;
    int p = blockIdx.x * 128 + threadIdx.x;
    for (int i = threadIdx.x; i < 4096; i += 128) {
        int j = i >> 9, ci = i & 511;
        ws[ci * 8 + j] = up_w[(co0 + j) * 512 + ci];
    }
    __syncthreads();
    ull a[4] = {0ull, 0ull, 0ull, 0ull};
    const float* xp = x1 + b * C1 * HWIN + p;
#pragma unroll 4
    for (int ci = 0; ci < 512; ci++) {
        float xv = __ldg(xp + ci * HWIN);
        ull xv2 = pack2(xv, xv);
        const ull* wr = (const ull*)(ws + ci * 8);
        fma2(a[0], wr[0], xv2);
        fma2(a[1], wr[1], xv2);
        fma2(a[2], wr[2], xv2);
        fma2(a[3], wr[3], xv2);
    }
#pragma unroll
    for (int jp = 0; jp < 4; jp++) {
        float2 u = unpack2(a[jp]);
        g_t[(b * CO + co0 + 2 * jp) * HWIN + p] = u.x;
        g_t[(b * CO + co0 + 2 * jp + 1) * HWIN + p] = u.y;
    }
}

// ---------------------------------------------------------------------------
// #2: fused copy (x2 -> g_x[0:256)) + bilinear upsample (g_t -> g_x[256:512))
#define COPY_BLKS 2048
__global__ void k_copyup(const float* __restrict__ x2,
                         const float* __restrict__ up_b) {
    int blk = blockIdx.x;
    if (blk < COPY_BLKS) {
        int i = blk * 256 + threadIdx.x;          // float4 index < 524288
        int b = i >> 18;
        int c = (i >> 10) & 255;
        int p4 = i & 1023;
        ((float4*)g_x)[((b * 512) + c) * 1024 + p4] = ((const float4*)x2)[i];
        return;
    }
    int idx = (blk - COPY_BLKS) * 256 + threadIdx.x;
    if (idx >= B_ * CO * HW) return;
    int p = idx & (HW - 1);
    int c = (idx >> 12) & (CO - 1);
    int b = idx >> 20;
    int h = p >> 6, w = p & 63;
    const float scale = 31.0f / 63.0f;
    float fh = h * scale;
    int i0 = (int)floorf(fh); if (i0 > 30) i0 = 30;
    float wy = fh - (float)i0;
    float fw = w * scale;
    int j0 = (int)floorf(fw); if (j0 > 30) j0 = 30;
    float wx = fw - (float)j0;
    const float* tt = g_t + (idx >> 12) * HWIN;
    float v00 = tt[i0 * 32 + j0];
    float v01 = tt[i0 * 32 + j0 + 1];
    float v10 = tt[(i0 + 1) * 32 + j0];
    float v11 = tt[(i0 + 1) * 32 + j0 + 1];
    float v = (1.f - wy) * ((1.f - wx) * v00 + wx * v01) +
              wy * ((1.f - wx) * v10 + wx * v11);
    g_x[((b * 512) + 256 + c) * HW + p] = v + up_b[c];
}

// ---------------------------------------------------------------------------
// #3: fused def_w transpose + offset-conv partials.
#define WT_BLKS 4608
__global__ void __launch_bounds__(256) k_offwt(const float* __restrict__ def_w,
                                               const float* __restrict__ off_w) {
    if (blockIdx.x < WT_BLKS) {
        int i = blockIdx.x * 256 + threadIdx.x;   // < K2*CC*CO
        int co = i & 255;
        int ci = (i >> 8) & 511;
        int k = i >> 17;
        g_wT[i] = def_w[(co * 512 + ci) * 9 + k];
        return;
    }
    __shared__ __align__(16) float xr[4][8][3][66];
    __shared__ __align__(16) float wsh[8][9 * 18];
    int r = blockIdx.x - WT_BLKS;                 // 0..127
    int b = r >> 6;
    int rr = r & 63;
    int cc = rr >> 4;
    int h0 = (rr & 15) * 4;
    int t = threadIdx.x;
    int g = t >> 6;                               // row group 0..3
    int tl = t & 63;
    int h = h0 + g;
    int ci0 = cc * 128;
    ull a[9];
#pragma unroll
    for (int c = 0; c < 9; c++) a[c] = 0ull;
    for (int s8 = 0; s8 < 128; s8 += 8) {
        for (int idx = t; idx < 8 * 162; idx += 256) {
            int ciL = idx / 162;
            int rem = idx - ciL * 162;
            int tap = rem / 18;
            int c = rem - tap * 18;
            int ci = ci0 + s8 + ciL;
            wsh[ciL][rem] = off_w[(c * 512 + ci) * 9 + tap];
        }
        for (int idx = tl; idx < 8 * 198; idx += 64) {
            int ciL = idx / 198;
            int rem = idx - ciL * 198;
            int rrow = rem / 66;
            int c66 = rem - rrow * 66;
            int cw = c66 - 1;
            int y = h - 1 + rrow;
            const float* pl = g_x + ((b * 512 + ci0 + s8 + ciL) << 12);
            xr[g][ciL][rrow][c66] = (y >= 0 && y < 64 && cw >= 0 && cw < 64)
                                        ? pl[y * 64 + cw] : 0.f;
        }
        __syncthreads();
#pragma unroll 2
        for (int ciL = 0; ciL < 8; ciL++) {
#pragma unroll
            for (int tap = 0; tap < 9; tap++) {
                float xv = xr[g][ciL][tap / 3][tl + tap % 3];
                ull xv2 = pack2(xv, xv);
                const ull* wr = (const ull*)&wsh[ciL][tap * 18];
#pragma unroll
                for (int c2 = 0; c2 < 9; c2++) fma2(a[c2], wr[c2], xv2);
            }
        }
        __syncthreads();
    }
#pragma unroll
    for (int c2 = 0; c2 < 9; c2++) {
        float2 u = unpack2(a[c2]);
        float* dst = g_offp + ((b * 4 + cc) * OFFC) * HW + h * 64 + tl;
        dst[(2 * c2) * HW] = u.x;
        dst[(2 * c2 + 1) * HW] = u.y;
    }
}

// ---------------------------------------------------------------------------
// #4: deformable conv, split-k over 3 tap-groups, software-pipelined (R5 inner).
// grid (256 pixel-tiles, 2 batch, 3 tap-groups); 128 threads.
// Thread t: co quad 4*(t&63), pixel slice (t>>6)*8. 24 (tap,chunk) iterations.
#define PIX 16
#define CICHUNK 64
#define NITER 24
__global__ void __launch_bounds__(128) k_deform(const float* __restrict__ off_b) {
    __shared__ __align__(16) float v_sh[2][CICHUNK][PIX];
    __shared__ __align__(16) int4 offs[3][PIX];
    __shared__ __align__(16) float4 cws[3][PIX];
    int b = blockIdx.y;
    int kg = blockIdx.z;
    int p0 = blockIdx.x * PIX;
    int t = threadIdx.x;
    int tco = t & 63;
    int tp = t >> 6;                 // 0..1 -> pixels tp*8..tp*8+7
    const float* xb = g_x + (b * 512) * HW;

    // Bilinear metadata for this group's 3 taps x 16 pixels.
    // Offset field = off_b + sum of 4 ci-chunk partials (inline reduction).
    for (int e = t; e < 3 * PIX; e += 128) {
        int kl = e >> 4;
        int k = kg * 3 + kl;
        int pi = e & 15;
        int p = p0 + pi;
        int h = p >> 6, w = p & 63;
        float dy = off_b[2 * k];
        float dx = off_b[2 * k + 1];
#pragma unroll
        for (int cc = 0; cc < 4; cc++) {
            const float* pp = g_offp + ((b * 4 + cc) * OFFC) * HW + p;
            dy += pp[(2 * k) * HW];
            dx += pp[(2 * k + 1) * HW];
        }
        float py = (float)h + (float)(k / 3) - 1.f + dy;
        float px = (float)w + (float)(k % 3) - 1.f + dx;
        float fy = floorf(py), fx = floorf(px);
        float wy = py - fy, wx = px - fx;
        int y0 = (int)fy, x0 = (int)fx;
        int y1 = y0 + 1, x1 = x0 + 1;
        bool vy0 = (unsigned)y0 < 64u, vy1 = (unsigned)y1 < 64u;
        bool vx0 = (unsigned)x0 < 64u, vx1 = (unsigned)x1 < 64u;
        int y0c = min(max(y0, 0), 63), y1c = min(max(y1, 0), 63);
        int x0c = min(max(x0, 0), 63), x1c = min(max(x1, 0), 63);
        cws[kl][pi] = make_float4((vy0 && vx0) ? (1.f - wy) * (1.f - wx) : 0.f,
                                  (vy0 && vx1) ? (1.f - wy) * wx : 0.f,
                                  (vy1 && vx0) ? wy * (1.f - wx) : 0.f,
                                  (vy1 && vx1) ? wy * wx : 0.f);
        offs[kl][pi] = make_int4(y0c * 64 + x0c, y0c * 64 + x1c,
                                 y1c * 64 + x0c, y1c * 64 + x1c);
    }
    __syncthreads();

    ull acc[4][4];
#pragma unroll
    for (int j = 0; j < 4; j++)
#pragma unroll
        for (int q = 0; q < 4; q++) acc[j][q] = 0ull;

    float r[32];
    // Prologue: gather iteration 0 (kl=0, c0=0) into buffer 0
#pragma unroll
    for (int j = 0; j < 8; j++) {
        int e = t + j * 128;
        int pi = e & 15;
        int cl = e >> 4;
        int4 o = offs[0][pi];
        const float* pl = xb + (cl << 12);
        r[4 * j + 0] = __ldg(pl + o.x);
        r[4 * j + 1] = __ldg(pl + o.y);
        r[4 * j + 2] = __ldg(pl + o.z);
        r[4 * j + 3] = __ldg(pl + o.w);
    }
#pragma unroll
    for (int j = 0; j < 8; j++) {
        int e = t + j * 128;
        int pi = e & 15;
        int cl = e >> 4;
        float4 cw = cws[0][pi];
        v_sh[0][cl][pi] = cw.x * r[4 * j] + cw.y * r[4 * j + 1] +
                          cw.z * r[4 * j + 2] + cw.w * r[4 * j + 3];
    }
    __syncthreads();

    int kl = 0, c0 = 0;
    for (int i = 0; i < NITER; i++) {
        int buf = i & 1;
        int kn = kl, c0n = c0 + CICHUNK;
        if (c0n == CC) { c0n = 0; kn = kl + 1; }
        // Gather LDGs for iteration i+1 (latency hidden by FMA below)
        if (i + 1 < NITER) {
            const float* basen = xb + c0n * HW;
#pragma unroll
            for (int j = 0; j < 8; j++) {
                int e = t + j * 128;
                int pi = e & 15;
                int cl = e >> 4;
                int4 o = offs[kn][pi];
                const float* pl = basen + (cl << 12);
                r[4 * j + 0] = __ldg(pl + o.x);
                r[4 * j + 1] = __ldg(pl + o.y);
                r[4 * j + 2] = __ldg(pl + o.z);
                r[4 * j + 3] = __ldg(pl + o.w);
            }
        }
        // FMA phase on current buffer
        const float4* wp =
            (const float4*)(g_wT + ((kg * 3 + kl) * CC + c0) * CO) + tco;
#pragma unroll 4
        for (int cl = 0; cl < CICHUNK; cl++) {
            float4 w = __ldg(wp + cl * 64);
            ull w0 = pack2(w.x, w.x);
            ull w1 = pack2(w.y, w.y);
            ull w2 = pack2(w.z, w.z);
            ull w3 = pack2(w.w, w.w);
            const ull* vv = (const ull*)&v_sh[buf][cl][tp * 8];
#pragma unroll
            for (int q = 0; q < 4; q++) {
                ull bq = vv[q];
                fma2(acc[0][q], w0, bq);
                fma2(acc[1][q], w1, bq);
                fma2(acc[2][q], w2, bq);
                fma2(acc[3][q], w3, bq);
            }
        }
        // Combine gathered corners into the other buffer
        if (i + 1 < NITER) {
#pragma unroll
            for (int j = 0; j < 8; j++) {
                int e = t + j * 128;
                int pi = e & 15;
                int cl = e >> 4;
                float4 cw = cws[kn][pi];
                v_sh[buf ^ 1][cl][pi] = cw.x * r[4 * j] + cw.y * r[4 * j + 1] +
                                        cw.z * r[4 * j + 2] + cw.w * r[4 * j + 3];
            }
        }
        __syncthreads();
        kl = kn; c0 = c0n;
    }

    // Epilogue: write tap-group partials (no bias; added in k_stats)
#pragma unroll
    for (int j = 0; j < 4; j++) {
        int co = 4 * tco + j;
        float* o = g_dcp + kg * BCOHW + (b * CO + co) * HW + p0 + tp * 8;
#pragma unroll
        for (int q = 0; q < 2; q++) {
            float2 u0 = unpack2(acc[j][2 * q]);
            float2 u1 = unpack2(acc[j][2 * q + 1]);
            ((float4*)o)[q] = make_float4(u0.x, u0.y, u1.x, u1.y);
        }
    }
}

// ---------------------------------------------------------------------------
// #5: reduce 3 tap-group partials + def_b -> g_dc, and BN stats
__global__ void k_stats(const float* __restrict__ def_b) {
    int co = blockIdx.x, t = threadIdx.x;
    float bb = def_b[co];
    float s = 0.f, s2 = 0.f;
#pragma unroll
    for (int b = 0; b < B_; b++) {
        int base = (b * CO + co) * HW;
        for (int i = t; i < HW; i += 256) {
            float v = bb + g_dcp[base + i] + g_dcp[BCOHW + base + i] +
                      g_dcp[2 * BCOHW + base + i];
            g_dc[base + i] = v;
            s += v; s2 += v * v;
        }
    }
    __shared__ float sh[256], sh2[256];
    sh[t] = s; sh2[t] = s2;
    __syncthreads();
    for (int o = 128; o > 0; o >>= 1) {
        if (t < o) { sh[t] += sh[t + o]; sh2[t] += sh2[t + o]; }
        __syncthreads();
    }
    if (t == 0) {
        float m = sh[0] * (1.f / 8192.f);
        float var = sh2[0] * (1.f / 8192.f) - m * m;
        g_stats[co] = m;
        g_stats[CO + co] = rsqrtf(var + 1e-5f);
    }
}

// ---------------------------------------------------------------------------
// #6: shortcut 1x1 conv + BN apply + relu
__global__ void k_final(const float* __restrict__ sc_w,
                        const float* __restrict__ sc_b,
                        const float* __restrict__ gamma,
                        const float* __restrict__ beta,
                        float* __restrict__ out) {
    __shared__ __align__(16) float ws[8 * 512];   // [ci][j]
    int b = blockIdx.z;
    int co0 = blockIdx.y * 8;
    int p = blockIdx.x * 128 + threadIdx.x;
    for (int i = threadIdx.x; i < 4096; i += 128) {
        int j = i >> 9, ci = i & 511;
        ws[ci * 8 + j] = sc_w[(co0 + j) * 512 + ci];
    }
    __syncthreads();
    ull a[4] = {0ull, 0ull, 0ull, 0ull};
    const float* xp = g_x + b * 512 * HW + p;
#pragma unroll 4
    for (int ci = 0; ci < 512; ci++) {
        float xv = __ldg(xp + ci * HW);
        ull xv2 = pack2(xv, xv);
        const ull* wr = (const ull*)(ws + ci * 8);
        fma2(a[0], wr[0], xv2);
        fma2(a[1], wr[1], xv2);
        fma2(a[2], wr[2], xv2);
        fma2(a[3], wr[3], xv2);
    }
#pragma unroll
    for (int jp = 0; jp < 4; jp++) {
        float2 u = unpack2(a[jp]);
#pragma unroll
        for (int half = 0; half < 2; half++) {
            int co = co0 + 2 * jp + half;
            float accv = half ? u.y : u.x;
            float m = g_stats[co], r = g_stats[CO + co];
            float v = (g_dc[(b * CO + co) * HW + p] - m) * r * gamma[co] +
                      beta[co] + accv + sc_b[co];
            out[(b * CO + co) * HW + p] = fmaxf(v, 0.f);
        }
    }
}

// ---------------------------------------------------------------------------
extern "C" void kernel_launch(void* const* d_in, const int* in_sizes, int n_in,
                              void* d_out, int out_size) {
    const float* x1    = (const float*)d_in[0];
    const float* x2    = (const float*)d_in[1];
    const float* up_w  = (const float*)d_in[2];
    const float* up_b  = (const float*)d_in[3];
    const float* off_w = (const float*)d_in[4];
    const float* off_b = (const float*)d_in[5];
    const float* def_w = (const float*)d_in[6];
    const float* def_b = (const float*)d_in[7];
    const float* bn_g  = (const float*)d_in[8];
    const float* bn_b  = (const float*)d_in[9];
    const float* sc_w  = (const float*)d_in[10];
    const float* sc_b  = (const float*)d_in[11];
    float* out = (float*)d_out;

    k_upconv<<<dim3(HWIN / 128, CO / 8, B_), 128>>>(x1, up_w);
    k_copyup<<<COPY_BLKS + (B_ * CO * HW + 255) / 256, 256>>>(x2, up_b);
    k_offwt<<<WT_BLKS + 128, 256>>>(def_w, off_w);
    k_deform<<<dim3(HW / PIX, B_, KG), 128>>>(off_b);
    k_stats<<<CO, 256>>>(def_b);
    k_final<<<dim3(HW / 128, CO / 8, B_), 128>>>(sc_w, sc_b, bn_g, bn_b, out);
}

// round 8
// speedup vs baseline: 1.3352x; 1.0651x over previous
#include <cuda_runtime.h>
#include <math.h>

// Problem constants
#define B_ 2
#define CC 512      // concat channels
#define CO 256      // output channels
#define C1 512      // x1 channels
#define H_ 64
#define W_ 64
#define HW 4096
#define HWIN 1024
#define OFFC 18
#define K2 9
#define KG 3        // tap groups (split-k)
#define BCOHW (B_ * CO * HW)

typedef unsigned long long ull;

// Packed f32x2 helpers (Blackwell FFMA2 path)
__device__ __forceinline__ ull pack2(float lo, float hi) {
    ull r; asm("mov.b64 %0, {%1,%2};" : "=l"(r) : "f"(lo), "f"(hi)); return r;
}
__device__ __forceinline__ void fma2(ull& d, ull a, ull b) {
    asm("fma.rn.f32x2 %0, %1, %2, %0;" : "+l"(d) : "l"(a), "l"(b));
}
__device__ __forceinline__ float2 unpack2(ull v) {
    float2 r; asm("mov.b64 {%0,%1}, %2;" : "=f"(r.x), "=f"(r.y) : "l"(v)); return r;
}

// Scratch (device globals; no runtime allocation)
__device__ float g_t[B_ * CO * HWIN];          // 1x1-conv'd x1 @ 32x32 (no bias)
__device__ __align__(16) float g_x[B_ * CC * HW];   // concat, NCHW
__device__ __align__(16) float g_xt[B_ * HW * CC];  // concat, NHWC (for gather)
__device__ float g_offp[B_ * 4 * OFFC * HW];   // offset partials (4 ci-chunks)
__device__ __align__(16) float g_dcp[KG * BCOHW];  // deform partials
__device__ float g_dc[BCOHW];                  // deform conv output (+def_b)
__device__ __align__(16) float g_wT[K2 * CC * CO + 256];  // def_w [k][ci][co]
__device__ float g_stats[2 * CO];              // mean, rstd per channel

// ---------------------------------------------------------------------------
// #1: 1x1 conv on x1 at 32x32 (transposed weight staging + FFMA2)
__global__ void k_upconv(const float* __restrict__ x1,
                         const float* __restrict__ up_w) {
    __shared__ __align__(16) float ws[8 * 512];   // [ci][j]
    int b = blockIdx.z;
    int co0 = blockIdx.y * 8;
    int p = blockIdx.x * 128 + threadIdx.x;
    for (int i = threadIdx.x; i < 4096; i += 128) {
        int j = i >> 9, ci = i & 511;
        ws[ci * 8 + j] = up_w[(co0 + j) * 512 + ci];
    }
    __syncthreads();
    ull a[4] = {0ull, 0ull, 0ull, 0ull};
    const float* xp = x1 + b * C1 * HWIN + p;
#pragma unroll 4
    for (int ci = 0; ci < 512; ci++) {
        float xv = __ldg(xp + ci * HWIN);
        ull xv2 = pack2(xv, xv);
        const ull* wr = (const ull*)(ws + ci * 8);
        fma2(a[0], wr[0], xv2);
        fma2(a[1], wr[1], xv2);
        fma2(a[2], wr[2], xv2);
        fma2(a[3], wr[3], xv2);
    }
#pragma unroll
    for (int jp = 0; jp < 4; jp++) {
        float2 u = unpack2(a[jp]);
        g_t[(b * CO + co0 + 2 * jp) * HWIN + p] = u.x;
        g_t[(b * CO + co0 + 2 * jp + 1) * HWIN + p] = u.y;
    }
}

// ---------------------------------------------------------------------------
// #2: fused copy (x2 -> g_x[0:256)) + bilinear upsample (-> g_x[256:512))
#define COPY_BLKS 2048
__global__ void k_copyup(const float* __restrict__ x2,
                         const float* __restrict__ up_b) {
    int blk = blockIdx.x;
    if (blk < COPY_BLKS) {
        int i = blk * 256 + threadIdx.x;          // float4 index < 524288
        int b = i >> 18;
        int c = (i >> 10) & 255;
        int p4 = i & 1023;
        ((float4*)g_x)[((b * 512) + c) * 1024 + p4] = ((const float4*)x2)[i];
        return;
    }
    int idx = (blk - COPY_BLKS) * 256 + threadIdx.x;
    if (idx >= B_ * CO * HW) return;
    int p = idx & (HW - 1);
    int c = (idx >> 12) & (CO - 1);
    int b = idx >> 20;
    int h = p >> 6, w = p & 63;
    const float scale = 31.0f / 63.0f;
    float fh = h * scale;
    int i0 = (int)floorf(fh); if (i0 > 30) i0 = 30;
    float wy = fh - (float)i0;
    float fw = w * scale;
    int j0 = (int)floorf(fw); if (j0 > 30) j0 = 30;
    float wx = fw - (float)j0;
    const float* tt = g_t + (idx >> 12) * HWIN;
    float v00 = tt[i0 * 32 + j0];
    float v01 = tt[i0 * 32 + j0 + 1];
    float v10 = tt[(i0 + 1) * 32 + j0];
    float v11 = tt[(i0 + 1) * 32 + j0 + 1];
    float v = (1.f - wy) * ((1.f - wx) * v00 + wx * v01) +
              wy * ((1.f - wx) * v10 + wx * v11);
    g_x[((b * 512) + 256 + c) * HW + p] = v + up_b[c];
}

// ---------------------------------------------------------------------------
// #3: fused def_w transpose + offset-conv partials + NCHW->NHWC transpose.
#define WT_BLKS 4608
#define OFF_BLKS 128
#define TR_BLKS 4096
__global__ void __launch_bounds__(256) k_offwt(const float* __restrict__ def_w,
                                               const float* __restrict__ off_w) {
    int t = threadIdx.x;
    if (blockIdx.x < WT_BLKS) {
        int i = blockIdx.x * 256 + t;             // < K2*CC*CO
        int co = i & 255;
        int ci = (i >> 8) & 511;
        int k = i >> 17;
        g_wT[i] = def_w[(co * 512 + ci) * 9 + k];
        return;
    }
    if (blockIdx.x >= WT_BLKS + OFF_BLKS) {
        // NHWC transpose: g_x[b][c][p] -> g_xt[b][p][c], 32x32 tiles
        __shared__ float tile[32][33];
        int r2 = blockIdx.x - (WT_BLKS + OFF_BLKS);   // 0..4095
        int b = r2 >> 11;
        int tt2 = r2 & 2047;
        int pt = tt2 >> 4;                            // 0..127 pixel tile
        int ct = tt2 & 15;                            // 0..15 channel tile (x32)
        int tx = t & 31, ty = t >> 5;                 // 0..7
#pragma unroll
        for (int i = 0; i < 4; i++) {
            int c = ct * 32 + ty + i * 8;
            tile[ty + i * 8][tx] = g_x[(b * 512 + c) * HW + pt * 32 + tx];
        }
        __syncthreads();
#pragma unroll
        for (int i = 0; i < 4; i++) {
            int p = pt * 32 + ty + i * 8;
            g_xt[(b * HW + p) * 512 + ct * 32 + tx] = tile[tx][ty + i * 8];
        }
        return;
    }
    __shared__ __align__(16) float xr[4][8][3][66];
    __shared__ __align__(16) float wsh[8][9 * 18];
    int r = blockIdx.x - WT_BLKS;                 // 0..127
    int b = r >> 6;
    int rr = r & 63;
    int cc = rr >> 4;
    int h0 = (rr & 15) * 4;
    int g = t >> 6;                               // row group 0..3
    int tl = t & 63;
    int h = h0 + g;
    int ci0 = cc * 128;
    ull a[9];
#pragma unroll
    for (int c = 0; c < 9; c++) a[c] = 0ull;
    for (int s8 = 0; s8 < 128; s8 += 8) {
        for (int idx = t; idx < 8 * 162; idx += 256) {
            int ciL = idx / 162;
            int rem = idx - ciL * 162;
            int tap = rem / 18;
            int c = rem - tap * 18;
            int ci = ci0 + s8 + ciL;
            wsh[ciL][rem] = off_w[(c * 512 + ci) * 9 + tap];
        }
        for (int idx = tl; idx < 8 * 198; idx += 64) {
            int ciL = idx / 198;
            int rem = idx - ciL * 198;
            int rrow = rem / 66;
            int c66 = rem - rrow * 66;
            int cw = c66 - 1;
            int y = h - 1 + rrow;
            const float* pl = g_x + ((b * 512 + ci0 + s8 + ciL) << 12);
            xr[g][ciL][rrow][c66] = (y >= 0 && y < 64 && cw >= 0 && cw < 64)
                                        ? pl[y * 64 + cw] : 0.f;
        }
        __syncthreads();
#pragma unroll 2
        for (int ciL = 0; ciL < 8; ciL++) {
#pragma unroll
            for (int tap = 0; tap < 9; tap++) {
                float xv = xr[g][ciL][tap / 3][tl + tap % 3];
                ull xv2 = pack2(xv, xv);
                const ull* wr = (const ull*)&wsh[ciL][tap * 18];
#pragma unroll
                for (int c2 = 0; c2 < 9; c2++) fma2(a[c2], wr[c2], xv2);
            }
        }
        __syncthreads();
    }
#pragma unroll
    for (int c2 = 0; c2 < 9; c2++) {
        float2 u = unpack2(a[c2]);
        float* dst = g_offp + ((b * 4 + cc) * OFFC) * HW + h * 64 + tl;
        dst[(2 * c2) * HW] = u.x;
        dst[(2 * c2 + 1) * HW] = u.y;
    }
}

// ---------------------------------------------------------------------------
// #4: deformable conv, split-k over 3 tap-groups, pipelined, COALESCED gather
// via NHWC g_xt. grid (256, 2, 3); 128 threads.
// Gather: lane = ci-within-chunk (cl), warp-pair = pixel half -> each corner
// load reads 32 contiguous floats (1 line/warp).
// FMA: thread t -> co quad 4*(t&63), pixel slice (t>>6)*8, FFMA2 pixel pairs.
#define PIX 16
#define CICHUNK 64
#define VPAD 18
#define NITER 24
__global__ void __launch_bounds__(128) k_deform(const float* __restrict__ off_b) {
    __shared__ __align__(16) float v_sh[2][CICHUNK][VPAD];
    __shared__ __align__(16) int4 offs[3][PIX];   // corner pixel idx << 9
    __shared__ __align__(16) float4 cws[3][PIX];
    int b = blockIdx.y;
    int kg = blockIdx.z;
    int p0 = blockIdx.x * PIX;
    int t = threadIdx.x;
    int tco = t & 63;
    int tp = t >> 6;                 // 0..1
    int cl = t & 63;                 // gather: ci within chunk
    int php = t >> 6;                // gather: pixel half
    const float* xt = g_xt + b * (HW * 512);

    // Bilinear metadata; offset field = off_b + 4 ci-chunk partials
    for (int e = t; e < 3 * PIX; e += 128) {
        int kl = e >> 4;
        int k = kg * 3 + kl;
        int pi = e & 15;
        int p = p0 + pi;
        int h = p >> 6, w = p & 63;
        float dy = off_b[2 * k];
        float dx = off_b[2 * k + 1];
#pragma unroll
        for (int cc = 0; cc < 4; cc++) {
            const float* pp = g_offp + ((b * 4 + cc) * OFFC) * HW + p;
            dy += pp[(2 * k) * HW];
            dx += pp[(2 * k + 1) * HW];
        }
        float py = (float)h + (float)(k / 3) - 1.f + dy;
        float px = (float)w + (float)(k % 3) - 1.f + dx;
        float fy = floorf(py), fx = floorf(px);
        float wy = py - fy, wx = px - fx;
        int y0 = (int)fy, x0 = (int)fx;
        int y1 = y0 + 1, x1 = x0 + 1;
        bool vy0 = (unsigned)y0 < 64u, vy1 = (unsigned)y1 < 64u;
        bool vx0 = (unsigned)x0 < 64u, vx1 = (unsigned)x1 < 64u;
        int y0c = min(max(y0, 0), 63), y1c = min(max(y1, 0), 63);
        int x0c = min(max(x0, 0), 63), x1c = min(max(x1, 0), 63);
        cws[kl][pi] = make_float4((vy0 && vx0) ? (1.f - wy) * (1.f - wx) : 0.f,
                                  (vy0 && vx1) ? (1.f - wy) * wx : 0.f,
                                  (vy1 && vx0) ? wy * (1.f - wx) : 0.f,
                                  (vy1 && vx1) ? wy * wx : 0.f);
        offs[kl][pi] = make_int4((y0c * 64 + x0c) << 9, (y0c * 64 + x1c) << 9,
                                 (y1c * 64 + x0c) << 9, (y1c * 64 + x1c) << 9);
    }
    __syncthreads();

    ull acc[4][4];
#pragma unroll
    for (int j = 0; j < 4; j++)
#pragma unroll
        for (int q = 0; q < 4; q++) acc[j][q] = 0ull;

    float r[32];
    // Prologue: gather (kl=0, c0=0) into buffer 0
    {
        const float* basec = xt + cl;
#pragma unroll
        for (int pass = 0; pass < 8; pass++) {
            int pi = php * 8 + pass;
            int4 o = offs[0][pi];
            r[4 * pass + 0] = __ldg(basec + o.x);
            r[4 * pass + 1] = __ldg(basec + o.y);
            r[4 * pass + 2] = __ldg(basec + o.z);
            r[4 * pass + 3] = __ldg(basec + o.w);
        }
#pragma unroll
        for (int pass = 0; pass < 8; pass++) {
            int pi = php * 8 + pass;
            float4 cw = cws[0][pi];
            v_sh[0][cl][pi] = cw.x * r[4 * pass] + cw.y * r[4 * pass + 1] +
                              cw.z * r[4 * pass + 2] + cw.w * r[4 * pass + 3];
        }
    }
    __syncthreads();

    int kl = 0, c0 = 0;
    for (int i = 0; i < NITER; i++) {
        int buf = i & 1;
        int kn = kl, c0n = c0 + CICHUNK;
        if (c0n == CC) { c0n = 0; kn = kl + 1; }
        // Coalesced gather LDGs for iteration i+1
        if (i + 1 < NITER) {
            const float* basec = xt + c0n + cl;
#pragma unroll
            for (int pass = 0; pass < 8; pass++) {
                int pi = php * 8 + pass;
                int4 o = offs[kn][pi];
                r[4 * pass + 0] = __ldg(basec + o.x);
                r[4 * pass + 1] = __ldg(basec + o.y);
                r[4 * pass + 2] = __ldg(basec + o.z);
                r[4 * pass + 3] = __ldg(basec + o.w);
            }
        }
        // FMA phase on current buffer
        const float4* wp =
            (const float4*)(g_wT + ((kg * 3 + kl) * CC + c0) * CO) + tco;
#pragma unroll 4
        for (int c = 0; c < CICHUNK; c++) {
            float4 w = __ldg(wp + c * 64);
            ull w0 = pack2(w.x, w.x);
            ull w1 = pack2(w.y, w.y);
            ull w2 = pack2(w.z, w.z);
            ull w3 = pack2(w.w, w.w);
            const ull* vv = (const ull*)&v_sh[buf][c][tp * 8];
#pragma unroll
            for (int q = 0; q < 4; q++) {
                ull bq = vv[q];
                fma2(acc[0][q], w0, bq);
                fma2(acc[1][q], w1, bq);
                fma2(acc[2][q], w2, bq);
                fma2(acc[3][q], w3, bq);
            }
        }
        // Combine gathered corners into the other buffer
        if (i + 1 < NITER) {
#pragma unroll
            for (int pass = 0; pass < 8; pass++) {
                int pi = php * 8 + pass;
                float4 cw = cws[kn][pi];
                v_sh[buf ^ 1][cl][pi] =
                    cw.x * r[4 * pass] + cw.y * r[4 * pass + 1] +
                    cw.z * r[4 * pass + 2] + cw.w * r[4 * pass + 3];
            }
        }
        __syncthreads();
        kl = kn; c0 = c0n;
    }

    // Epilogue: write tap-group partials
#pragma unroll
    for (int j = 0; j < 4; j++) {
        int co = 4 * tco + j;
        float* o = g_dcp + kg * BCOHW + (b * CO + co) * HW + p0 + tp * 8;
#pragma unroll
        for (int q = 0; q < 2; q++) {
            float2 u0 = unpack2(acc[j][2 * q]);
            float2 u1 = unpack2(acc[j][2 * q + 1]);
            ((float4*)o)[q] = make_float4(u0.x, u0.y, u1.x, u1.y);
        }
    }
}

// ---------------------------------------------------------------------------
// #5: reduce 3 tap-group partials + def_b -> g_dc, and BN stats
__global__ void k_stats(const float* __restrict__ def_b) {
    int co = blockIdx.x, t = threadIdx.x;
    float bb = def_b[co];
    float s = 0.f, s2 = 0.f;
#pragma unroll
    for (int b = 0; b < B_; b++) {
        int base = (b * CO + co) * HW;
        for (int i = t; i < HW; i += 256) {
            float v = bb + g_dcp[base + i] + g_dcp[BCOHW + base + i] +
                      g_dcp[2 * BCOHW + base + i];
            g_dc[base + i] = v;
            s += v; s2 += v * v;
        }
    }
    __shared__ float sh[256], sh2[256];
    sh[t] = s; sh2[t] = s2;
    __syncthreads();
    for (int o = 128; o > 0; o >>= 1) {
        if (t < o) { sh[t] += sh[t + o]; sh2[t] += sh2[t + o]; }
        __syncthreads();
    }
    if (t == 0) {
        float m = sh[0] * (1.f / 8192.f);
        float var = sh2[0] * (1.f / 8192.f) - m * m;
        g_stats[co] = m;
        g_stats[CO + co] = rsqrtf(var + 1e-5f);
    }
}

// ---------------------------------------------------------------------------
// #6: shortcut 1x1 conv + BN apply + relu
__global__ void k_final(const float* __restrict__ sc_w,
                        const float* __restrict__ sc_b,
                        const float* __restrict__ gamma,
                        const float* __restrict__ beta,
                        float* __restrict__ out) {
    __shared__ __align__(16) float ws[8 * 512];   // [ci][j]
    int b = blockIdx.z;
    int co0 = blockIdx.y * 8;
    int p = blockIdx.x * 128 + threadIdx.x;
    for (int i = threadIdx.x; i < 4096; i += 128) {
        int j = i >> 9, ci = i & 511;
        ws[ci * 8 + j] = sc_w[(co0 + j) * 512 + ci];
    }
    __syncthreads();
    ull a[4] = {0ull, 0ull, 0ull, 0ull};
    const float* xp = g_x + b * 512 * HW + p;
#pragma unroll 4
    for (int ci = 0; ci < 512; ci++) {
        float xv = __ldg(xp + ci * HW);
        ull xv2 = pack2(xv, xv);
        const ull* wr = (const ull*)(ws + ci * 8);
        fma2(a[0], wr[0], xv2);
        fma2(a[1], wr[1], xv2);
        fma2(a[2], wr[2], xv2);
        fma2(a[3], wr[3], xv2);
    }
#pragma unroll
    for (int jp = 0; jp < 4; jp++) {
        float2 u = unpack2(a[jp]);
#pragma unroll
        for (int half = 0; half < 2; half++) {
            int co = co0 + 2 * jp + half;
            float accv = half ? u.y : u.x;
            float m = g_stats[co], r = g_stats[CO + co];
            float v = (g_dc[(b * CO + co) * HW + p] - m) * r * gamma[co] +
                      beta[co] + accv + sc_b[co];
            out[(b * CO + co) * HW + p] = fmaxf(v, 0.f);
        }
    }
}

// ---------------------------------------------------------------------------
extern "C" void kernel_launch(void* const* d_in, const int* in_sizes, int n_in,
                              void* d_out, int out_size) {
    const float* x1    = (const float*)d_in[0];
    const float* x2    = (const float*)d_in[1];
    const float* up_w  = (const float*)d_in[2];
    const float* up_b  = (const float*)d_in[3];
    const float* off_w = (const float*)d_in[4];
    const float* off_b = (const float*)d_in[5];
    const float* def_w = (const float*)d_in[6];
    const float* def_b = (const float*)d_in[7];
    const float* bn_g  = (const float*)d_in[8];
    const float* bn_b  = (const float*)d_in[9];
    const float* sc_w  = (const float*)d_in[10];
    const float* sc_b  = (const float*)d_in[11];
    float* out = (float*)d_out;

    k_upconv<<<dim3(HWIN / 128, CO / 8, B_), 128>>>(x1, up_w);
    k_copyup<<<COPY_BLKS + (B_ * CO * HW + 255) / 256, 256>>>(x2, up_b);
    k_offwt<<<WT_BLKS + OFF_BLKS + TR_BLKS, 256>>>(def_w, off_w);
    k_deform<<<dim3(HW / PIX, B_, KG), 128>>>(off_b);
    k_stats<<<CO, 256>>>(def_b);
    k_final<<<dim3(HW / 128, CO / 8, B_), 128>>>(sc_w, sc_b, bn_g, bn_b, out);
}